// round 13
// baseline (speedup 1.0000x reference)
#include <cuda_runtime.h>
#include <cstdint>

// IPLayer segment-sum: out[atom][g] += inter[pair][g] for atom = ind_2[pair][0]
// Inputs (metadata order): ind_2 (int32, N_PAIRS*2), prop (float32, N_ATOMS*128),
//                          inter (float32, N_PAIRS*64). Output: float32 N_ATOMS*64.
//
// Fused persistent kernel: phase 1 zeroes the output grid-stride, a software
// grid barrier (monotonic epoch counter -> safe across graph replays), then
// phase 2 runs the converged dense-sector red.v4 scatter as a grid-stride
// loop. Removes the memset node + one launch gap; scatter structure is the
// proven champion (16 lanes/row, PP=4 pairs/thread, ldcs streaming loads).

#define N_INTER 64
#define PP      4
#define NBLK    888   // <= 148 SMs * 8 resident CTAs (256thr/32reg) -> co-resident

__device__ unsigned long long g_bar = 0ULL;

__global__ void __launch_bounds__(256, 8) seg_fused_kernel(
        const int* __restrict__ ind2,
        const float4* __restrict__ inter,
        float* __restrict__ out,
        int n_pairs, int n_out4) {
    int tid = threadIdx.x;
    int gtid = blockIdx.x * blockDim.x + tid;
    int gsize = gridDim.x * blockDim.x;

    // ---- Phase 1: zero the (poisoned) output, grid-stride float4 stores ----
    float4 z = make_float4(0.f, 0.f, 0.f, 0.f);
    for (int i = gtid; i < n_out4; i += gsize)
        ((float4*)out)[i] = z;

    // ---- Grid barrier (monotonic epoch; deterministic across replays) ----
    __syncthreads();
    if (tid == 0) {
        __threadfence();                                   // publish zeros
        unsigned long long old = atomicAdd(&g_bar, 1ULL);
        unsigned long long target = (old / gridDim.x + 1ULL) * gridDim.x;
        while (atomicAdd(&g_bar, 0ULL) < target) { }       // acquire-ish spin
        __threadfence();
    }
    __syncthreads();

    // ---- Phase 2: scatter-add, grid-stride over pair-groups ----
    int c = tid & 15;                 // float4 chunk within the 64-float row
    int slot = tid >> 4;              // 16 groups per 256-thread CTA iteration
    long long n_groups = ((long long)n_pairs + PP - 1) / PP;

    for (long long g = (long long)blockIdx.x * 16 + slot; g < n_groups;
         g += (long long)gridDim.x * 16) {
        int p0 = (int)(g * PP);

        if (p0 + PP <= n_pairs) {
            int a0 = __ldcs(&ind2[2 * (p0 + 0)]);
            int a1 = __ldcs(&ind2[2 * (p0 + 1)]);
            int a2 = __ldcs(&ind2[2 * (p0 + 2)]);
            int a3 = __ldcs(&ind2[2 * (p0 + 3)]);

            const float4* src = inter + (size_t)p0 * (N_INTER / 4) + c;
            float4 v0 = __ldcs(src + 0 * (N_INTER / 4));
            float4 v1 = __ldcs(src + 1 * (N_INTER / 4));
            float4 v2 = __ldcs(src + 2 * (N_INTER / 4));
            float4 v3 = __ldcs(src + 3 * (N_INTER / 4));

            float* d0 = out + (size_t)a0 * N_INTER + c * 4;
            float* d1 = out + (size_t)a1 * N_INTER + c * 4;
            float* d2 = out + (size_t)a2 * N_INTER + c * 4;
            float* d3 = out + (size_t)a3 * N_INTER + c * 4;

            asm volatile("red.global.add.v4.f32 [%0], {%1,%2,%3,%4};"
                         :: "l"(d0), "f"(v0.x), "f"(v0.y), "f"(v0.z), "f"(v0.w) : "memory");
            asm volatile("red.global.add.v4.f32 [%0], {%1,%2,%3,%4};"
                         :: "l"(d1), "f"(v1.x), "f"(v1.y), "f"(v1.z), "f"(v1.w) : "memory");
            asm volatile("red.global.add.v4.f32 [%0], {%1,%2,%3,%4};"
                         :: "l"(d2), "f"(v2.x), "f"(v2.y), "f"(v2.z), "f"(v2.w) : "memory");
            asm volatile("red.global.add.v4.f32 [%0], {%1,%2,%3,%4};"
                         :: "l"(d3), "f"(v3.x), "f"(v3.y), "f"(v3.z), "f"(v3.w) : "memory");
        } else {
            for (int p = p0; p < n_pairs; p++) {
                int a = __ldcs(&ind2[2 * p]);
                float4 v = __ldcs(&inter[(size_t)p * (N_INTER / 4) + c]);
                float* dst = out + (size_t)a * N_INTER + c * 4;
                asm volatile("red.global.add.v4.f32 [%0], {%1,%2,%3,%4};"
                             :: "l"(dst), "f"(v.x), "f"(v.y), "f"(v.z), "f"(v.w) : "memory");
            }
        }
    }
}

extern "C" void kernel_launch(void* const* d_in, const int* in_sizes, int n_in,
                              void* d_out, int out_size) {
    const int*    ind2  = (const int*)d_in[0];
    const float4* inter = (const float4*)d_in[2];
    float*        out   = (float*)d_out;

    int n_pairs = in_sizes[0] / 2;
    int n_out4  = out_size / 4;

    seg_fused_kernel<<<NBLK, 256>>>(ind2, inter, out, n_pairs, n_out4);
}

// round 15
// speedup vs baseline: 1.3092x; 1.3092x over previous
#include <cuda_runtime.h>
#include <cstdint>

// IPLayer segment-sum: out[atom][g] += inter[pair][g] for atom = ind_2[pair][0]
// Inputs (metadata order): ind_2 (int32, N_PAIRS*2), prop (float32, N_ATOMS*128),
//                          inter (float32, N_PAIRS*64). Output: float32 N_ATOMS*64.
//
// Converged champion: dense-sector red.global.add.v4.f32 scatter.
// 16 lanes cover one pair's 256B row (one float4 chunk per lane -> every RED
// warp-instruction writes fully dense 32B sectors); each thread handles PP=4
// consecutive pairs (MLP>=4); streaming (ldcs) loads keep the one-touch 870MB
// stream from polluting L2 where the output rows live. Kernel runs at ~97% of
// the LTS aggregate-byte floor (~845MB reads + 819MB RED payload through L2 at
// ~6300 B/cyc). Block-per-data launch (NOT grid-stride/persistent): resident
// warps stream a contiguous window -> dense DRAM access (R13 showed -30%
// bandwidth otherwise).

#define N_INTER 64
#define PP      4   // pairs per thread

__global__ void zero_out_kernel(float4* __restrict__ out, int n4) {
    int i = blockIdx.x * blockDim.x + threadIdx.x;
    if (i < n4) out[i] = make_float4(0.f, 0.f, 0.f, 0.f);
}

__global__ void seg_red_kernel(const int* __restrict__ ind2,
                               const float4* __restrict__ inter,
                               float* __restrict__ out,
                               int n_pairs) {
    int i = blockIdx.x * blockDim.x + threadIdx.x;
    int g = i >> 4;          // pair-group index (PP pairs)
    int c = i & 15;          // float4 chunk within the 64-float row
    int p0 = g * PP;
    if (p0 >= n_pairs) return;

    if (p0 + PP <= n_pairs) {
        // Two 16B index loads cover pairs p0..p3 (both columns; we use col 0).
        // 32B-aligned since p0 % 4 == 0.
        int4 i01 = __ldcs((const int4*)&ind2[2 * p0]);      // p0: .x, p1: .z
        int4 i23 = __ldcs((const int4*)&ind2[2 * p0 + 4]);  // p2: .x, p3: .z
        int a0 = i01.x, a1 = i01.z, a2 = i23.x, a3 = i23.z;

        // Streaming (evict-first) row loads: one-touch data, keep out of L2.
        const float4* src = inter + (size_t)p0 * (N_INTER / 4) + c;
        float4 v0 = __ldcs(src + 0 * (N_INTER / 4));
        float4 v1 = __ldcs(src + 1 * (N_INTER / 4));
        float4 v2 = __ldcs(src + 2 * (N_INTER / 4));
        float4 v3 = __ldcs(src + 3 * (N_INTER / 4));

        float* d0 = out + (size_t)a0 * N_INTER + c * 4;
        float* d1 = out + (size_t)a1 * N_INTER + c * 4;
        float* d2 = out + (size_t)a2 * N_INTER + c * 4;
        float* d3 = out + (size_t)a3 * N_INTER + c * 4;

        asm volatile("red.global.add.v4.f32 [%0], {%1,%2,%3,%4};"
                     :: "l"(d0), "f"(v0.x), "f"(v0.y), "f"(v0.z), "f"(v0.w) : "memory");
        asm volatile("red.global.add.v4.f32 [%0], {%1,%2,%3,%4};"
                     :: "l"(d1), "f"(v1.x), "f"(v1.y), "f"(v1.z), "f"(v1.w) : "memory");
        asm volatile("red.global.add.v4.f32 [%0], {%1,%2,%3,%4};"
                     :: "l"(d2), "f"(v2.x), "f"(v2.y), "f"(v2.z), "f"(v2.w) : "memory");
        asm volatile("red.global.add.v4.f32 [%0], {%1,%2,%3,%4};"
                     :: "l"(d3), "f"(v3.x), "f"(v3.y), "f"(v3.z), "f"(v3.w) : "memory");
    } else {
        // Tail: per-pair.
        for (int p = p0; p < n_pairs; p++) {
            int a = __ldcs(&ind2[2 * p]);
            float4 v = __ldcs(&inter[(size_t)p * (N_INTER / 4) + c]);
            float* dst = out + (size_t)a * N_INTER + c * 4;
            asm volatile("red.global.add.v4.f32 [%0], {%1,%2,%3,%4};"
                         :: "l"(dst), "f"(v.x), "f"(v.y), "f"(v.z), "f"(v.w) : "memory");
        }
    }
}

extern "C" void kernel_launch(void* const* d_in, const int* in_sizes, int n_in,
                              void* d_out, int out_size) {
    const int*    ind2  = (const int*)d_in[0];
    const float4* inter = (const float4*)d_in[2];
    float*        out   = (float*)d_out;

    int n_pairs = in_sizes[0] / 2;

    // Zero the (poisoned) output; plain stores allocate the rows in L2
    // where the subsequent REDs hit.
    int n4 = out_size / 4;
    zero_out_kernel<<<(n4 + 255) / 256, 256>>>((float4*)out, n4);

    // Scatter-add: 16 lanes x PP pairs per thread, block-per-data launch.
    int n_groups = (n_pairs + PP - 1) / PP;
    long long n_work = (long long)n_groups * 16;
    int blocks = (int)((n_work + 255) / 256);
    seg_red_kernel<<<blocks, 256>>>(ind2, inter, out, n_pairs);
}

// round 16
// speedup vs baseline: 1.3118x; 1.0020x over previous
#include <cuda_runtime.h>
#include <cstdint>

// IPLayer segment-sum: out[atom][g] += inter[pair][g] for atom = ind_2[pair][0]
// Inputs (metadata order): ind_2 (int32, N_PAIRS*2), prop (float32, N_ATOMS*128),
//                          inter (float32, N_PAIRS*64). Output: float32 N_ATOMS*64.
//
// Converged champion: dense-sector red.global.add.v4.f32 scatter.
// 16 lanes per 256B row (dense 32B sectors in every RED warp-instruction),
// PP=4 pairs/thread (MLP>=4), ldcs streaming loads, block-per-data launch.
// Kernel is pinned at ~97% of the LTS aggregate-byte floor (~845MB reads +
// 819MB RED payload through L2 at ~6300 B/cyc); occupancy/MLP/cache-hint/TMA/
// CSR/fusion variants all confirmed byte-bound. This round: 1024-thread
// scatter blocks (4x fewer blocks, same occupancy) as a final noise-level trim.

#define N_INTER 64
#define PP      4   // pairs per thread

__global__ void zero_out_kernel(float4* __restrict__ out, int n4) {
    int i = blockIdx.x * blockDim.x + threadIdx.x;
    if (i < n4) out[i] = make_float4(0.f, 0.f, 0.f, 0.f);
}

__global__ void __launch_bounds__(1024) seg_red_kernel(
        const int* __restrict__ ind2,
        const float4* __restrict__ inter,
        float* __restrict__ out,
        int n_pairs) {
    int i = blockIdx.x * blockDim.x + threadIdx.x;
    int g = i >> 4;          // pair-group index (PP pairs)
    int c = i & 15;          // float4 chunk within the 64-float row
    int p0 = g * PP;
    if (p0 >= n_pairs) return;

    if (p0 + PP <= n_pairs) {
        // Two 16B index loads cover pairs p0..p3 (32B-aligned since p0 % 4 == 0).
        int4 i01 = __ldcs((const int4*)&ind2[2 * p0]);      // p0: .x, p1: .z
        int4 i23 = __ldcs((const int4*)&ind2[2 * p0 + 4]);  // p2: .x, p3: .z
        int a0 = i01.x, a1 = i01.z, a2 = i23.x, a3 = i23.z;

        // Streaming (evict-first) row loads: one-touch data, keep out of L2.
        const float4* src = inter + (size_t)p0 * (N_INTER / 4) + c;
        float4 v0 = __ldcs(src + 0 * (N_INTER / 4));
        float4 v1 = __ldcs(src + 1 * (N_INTER / 4));
        float4 v2 = __ldcs(src + 2 * (N_INTER / 4));
        float4 v3 = __ldcs(src + 3 * (N_INTER / 4));

        float* d0 = out + (size_t)a0 * N_INTER + c * 4;
        float* d1 = out + (size_t)a1 * N_INTER + c * 4;
        float* d2 = out + (size_t)a2 * N_INTER + c * 4;
        float* d3 = out + (size_t)a3 * N_INTER + c * 4;

        asm volatile("red.global.add.v4.f32 [%0], {%1,%2,%3,%4};"
                     :: "l"(d0), "f"(v0.x), "f"(v0.y), "f"(v0.z), "f"(v0.w) : "memory");
        asm volatile("red.global.add.v4.f32 [%0], {%1,%2,%3,%4};"
                     :: "l"(d1), "f"(v1.x), "f"(v1.y), "f"(v1.z), "f"(v1.w) : "memory");
        asm volatile("red.global.add.v4.f32 [%0], {%1,%2,%3,%4};"
                     :: "l"(d2), "f"(v2.x), "f"(v2.y), "f"(v2.z), "f"(v2.w) : "memory");
        asm volatile("red.global.add.v4.f32 [%0], {%1,%2,%3,%4};"
                     :: "l"(d3), "f"(v3.x), "f"(v3.y), "f"(v3.z), "f"(v3.w) : "memory");
    } else {
        // Tail: per-pair.
        for (int p = p0; p < n_pairs; p++) {
            int a = __ldcs(&ind2[2 * p]);
            float4 v = __ldcs(&inter[(size_t)p * (N_INTER / 4) + c]);
            float* dst = out + (size_t)a * N_INTER + c * 4;
            asm volatile("red.global.add.v4.f32 [%0], {%1,%2,%3,%4};"
                         :: "l"(dst), "f"(v.x), "f"(v.y), "f"(v.z), "f"(v.w) : "memory");
        }
    }
}

extern "C" void kernel_launch(void* const* d_in, const int* in_sizes, int n_in,
                              void* d_out, int out_size) {
    const int*    ind2  = (const int*)d_in[0];
    const float4* inter = (const float4*)d_in[2];
    float*        out   = (float*)d_out;

    int n_pairs = in_sizes[0] / 2;

    // Zero the (poisoned) output; plain stores allocate the rows in L2
    // where the subsequent REDs hit.
    int n4 = out_size / 4;
    zero_out_kernel<<<(n4 + 511) / 512, 512>>>((float4*)out, n4);

    // Scatter-add: 16 lanes x PP pairs per thread, block-per-data launch.
    int n_groups = (n_pairs + PP - 1) / PP;
    long long n_work = (long long)n_groups * 16;
    int blocks = (int)((n_work + 1023) / 1024);
    seg_red_kernel<<<blocks, 1024>>>(ind2, inter, out, n_pairs);
}